// round 7
// baseline (speedup 1.0000x reference)
#include <cuda_runtime.h>
#include <math.h>

#define NUM_E 640000
#define NUM_N 20000
#define NUM_H 8

// Scratch (allocation-free rule: __device__ globals)
__device__ __align__(16) float g_tscore[NUM_N * NUM_H];  // x_e[t] . w[h,16:]
__device__ __align__(16) float g_segsum[NUM_N * NUM_H];  // sum(exp) then recip

// ---------------------------------------------------------------------------
// K1: per-node target scores + zero segsum. One warp per 4 nodes.
#define NODES_PER_WARP 4
__global__ void k_tscore(const float* __restrict__ x_e,
                         const float* __restrict__ weight) {
    int gtid = blockIdx.x * blockDim.x + threadIdx.x;
    int warp = gtid >> 5;
    int lane = gtid & 31;
    int n0 = warp * NODES_PER_WARP;
    if (n0 >= NUM_N) return;

    const float4* x4p = reinterpret_cast<const float4*>(x_e);
    float4 x[NODES_PER_WARP];
#pragma unroll
    for (int i = 0; i < NODES_PER_WARP; i++)
        x[i] = x4p[(size_t)(n0 + i) * 32 + lane];

    int h = lane >> 2, q = lane & 3;
    float4 w4 = reinterpret_cast<const float4*>(weight)[h * 8 + 4 + q];

#pragma unroll
    for (int i = 0; i < NODES_PER_WARP; i++) {
        float p = x[i].x * w4.x + x[i].y * w4.y + x[i].z * w4.z + x[i].w * w4.w;
        p += __shfl_xor_sync(0xffffffffu, p, 1);
        p += __shfl_xor_sync(0xffffffffu, p, 2);
        if (q == 0) {
            g_tscore[(n0 + i) * NUM_H + h] = p;
            g_segsum[(n0 + i) * NUM_H + h] = 0.0f;
        }
    }
}

// ---------------------------------------------------------------------------
// K2: fused copy + dot + LeakyReLU + exp + vector alpha store + vector
// red.add segsum. One warp per 4 edges.
#define EDGES_PER_WARP 4
__global__ void k_edge(const float* __restrict__ message,
                       const int* __restrict__ target,
                       const float* __restrict__ weight,
                       float* __restrict__ out_msg,
                       float* __restrict__ out_alpha) {
    int gtid = blockIdx.x * blockDim.x + threadIdx.x;
    int warp = gtid >> 5;
    int lane = gtid & 31;
    int e0 = warp * EDGES_PER_WARP;
    if (e0 >= NUM_E) return;

    const float4* msg4 = reinterpret_cast<const float4*>(message);
    float4*       out4 = reinterpret_cast<float4*>(out_msg);

    float4 m[EDGES_PER_WARP];
#pragma unroll
    for (int i = 0; i < EDGES_PER_WARP; i++)
        m[i] = __ldcs(&msg4[(size_t)(e0 + i) * 32 + lane]);   // streaming read
#pragma unroll
    for (int i = 0; i < EDGES_PER_WARP; i++)
        __stcs(&out4[(size_t)(e0 + i) * 32 + lane], m[i]);    // streaming write

    int h = lane >> 2, q = lane & 3;
    float4 w4 = reinterpret_cast<const float4*>(weight)[h * 8 + q];  // msg half
    unsigned base = lane & 16;   // collector lanes 0 and 16
    int half = lane >> 4;        // 0 -> heads 0-3, 1 -> heads 4-7

    float4* alpha4 = reinterpret_cast<float4*>(out_alpha);

#pragma unroll
    for (int i = 0; i < EDGES_PER_WARP; i++) {
        int e = e0 + i;
        float p = m[i].x * w4.x + m[i].y * w4.y + m[i].z * w4.z + m[i].w * w4.w;
        p += __shfl_xor_sync(0xffffffffu, p, 1);
        p += __shfl_xor_sync(0xffffffffu, p, 2);

        float ex = 0.0f;
        int   t  = 0;
        if (q == 0) {                      // lanes 0,4,...,28: one head each
            t = target[e];
            float s = p + g_tscore[t * NUM_H + h];
            s = (s >= 0.0f) ? s : 0.01f * s;     // LeakyReLU
            ex = __expf(s);                      // no max-shift (safe range)
        }

        // Gather 4 heads' ex onto collector lanes 0 (h0-3) and 16 (h4-7).
        float v0 = __shfl_sync(0xffffffffu, ex, base + 0);
        float v1 = __shfl_sync(0xffffffffu, ex, base + 4);
        float v2 = __shfl_sync(0xffffffffu, ex, base + 8);
        float v3 = __shfl_sync(0xffffffffu, ex, base + 12);
        int   tt = __shfl_sync(0xffffffffu, t,  base);

        if ((lane & 15) == 0) {
            float4 v = make_float4(v0, v1, v2, v3);
            alpha4[e * 2 + half] = v;  // plain store: keep L2-resident for k_norm
            asm volatile("red.global.add.v4.f32 [%0], {%1, %2, %3, %4};"
                         :: "l"(&g_segsum[tt * NUM_H + half * 4]),
                            "f"(v0), "f"(v1), "f"(v2), "f"(v3)
                         : "memory");
        }
    }
}

// ---------------------------------------------------------------------------
// K2.5: reciprocal of segment sums (turns k_norm divisions into multiplies)
__global__ void k_recip() {
    int i = blockIdx.x * blockDim.x + threadIdx.x;
    if (i < NUM_N * NUM_H)
        g_segsum[i] = 1.0f / (g_segsum[i] + 1e-16f);
}

// ---------------------------------------------------------------------------
// K3: normalize alpha. 2 edges per thread (320k threads); independent loads
// (targets + alphas) issued before the target-dependent gathers.
#define NORM_EPT 2
__global__ void k_norm(const int* __restrict__ target,
                       float* __restrict__ out_alpha) {
    const int S = NUM_E / NORM_EPT;  // 320000
    int tid = blockIdx.x * blockDim.x + threadIdx.x;
    if (tid >= S) return;

    int e0 = tid;
    int e1 = tid + S;

    int t0 = target[e0];
    int t1 = target[e1];

    float4* a4 = reinterpret_cast<float4*>(out_alpha);
    float4 a00 = a4[e0 * 2 + 0];
    float4 a01 = a4[e0 * 2 + 1];
    float4 a10 = a4[e1 * 2 + 0];
    float4 a11 = a4[e1 * 2 + 1];

    const float4* rs4 = reinterpret_cast<const float4*>(g_segsum);
    float4 r00 = rs4[t0 * 2 + 0];
    float4 r01 = rs4[t0 * 2 + 1];
    float4 r10 = rs4[t1 * 2 + 0];
    float4 r11 = rs4[t1 * 2 + 1];

    a00.x *= r00.x; a00.y *= r00.y; a00.z *= r00.z; a00.w *= r00.w;
    a01.x *= r01.x; a01.y *= r01.y; a01.z *= r01.z; a01.w *= r01.w;
    a10.x *= r10.x; a10.y *= r10.y; a10.z *= r10.z; a10.w *= r10.w;
    a11.x *= r11.x; a11.y *= r11.y; a11.z *= r11.z; a11.w *= r11.w;

    __stcs(&a4[e0 * 2 + 0], a00);   // final output: streaming store
    __stcs(&a4[e0 * 2 + 1], a01);
    __stcs(&a4[e1 * 2 + 0], a10);
    __stcs(&a4[e1 * 2 + 1], a11);
}

// ---------------------------------------------------------------------------
extern "C" void kernel_launch(void* const* d_in, const int* in_sizes, int n_in,
                              void* d_out, int out_size) {
    const int*   edge_index = (const int*)d_in[0];    // (2, E) int32
    const float* message    = (const float*)d_in[1];  // (E, 128)
    const float* x_e        = (const float*)d_in[2];  // (N, 128)
    const float* weight     = (const float*)d_in[3];  // (8, 32)

    const int* target = edge_index + NUM_E;  // row 1

    float* out_msg   = (float*)d_out;                  // E*128 floats
    float* out_alpha = out_msg + (size_t)NUM_E * 128;  // E*8 floats

    const int TPB = 256;

    {   // k_tscore: one warp per 4 nodes
        int warps = (NUM_N + NODES_PER_WARP - 1) / NODES_PER_WARP;  // 5000
        k_tscore<<<(warps * 32 + TPB - 1) / TPB, TPB>>>(x_e, weight);
    }
    {   // k_edge: one warp per 4 edges
        int warps = NUM_E / EDGES_PER_WARP;              // 160000
        k_edge<<<(warps * 32 + TPB - 1) / TPB, TPB>>>(message, target, weight,
                                                      out_msg, out_alpha);
    }
    k_recip<<<(NUM_N * NUM_H + TPB - 1) / TPB, TPB>>>();
    k_norm<<<(NUM_E / NORM_EPT + TPB - 1) / TPB, TPB>>>(target, out_alpha);
}

// round 8
// speedup vs baseline: 1.0170x; 1.0170x over previous
#include <cuda_runtime.h>
#include <math.h>

#define NUM_E 640000
#define NUM_N 20000
#define NUM_H 8

// Scratch (allocation-free rule: __device__ globals)
__device__ __align__(16) float g_tscore[NUM_N * NUM_H];  // x_e[t] . w[h,16:]
__device__ __align__(16) float g_segsum[NUM_N * NUM_H];  // sum(exp) then recip

// ---------------------------------------------------------------------------
// K1: per-node target scores + zero segsum. One warp per 4 nodes.
#define NODES_PER_WARP 4
__global__ void k_tscore(const float* __restrict__ x_e,
                         const float* __restrict__ weight) {
    int gtid = blockIdx.x * blockDim.x + threadIdx.x;
    int warp = gtid >> 5;
    int lane = gtid & 31;
    int n0 = warp * NODES_PER_WARP;
    if (n0 >= NUM_N) return;

    const float4* x4p = reinterpret_cast<const float4*>(x_e);
    float4 x[NODES_PER_WARP];
#pragma unroll
    for (int i = 0; i < NODES_PER_WARP; i++)
        x[i] = x4p[(size_t)(n0 + i) * 32 + lane];

    int h = lane >> 2, q = lane & 3;
    float4 w4 = reinterpret_cast<const float4*>(weight)[h * 8 + 4 + q];

#pragma unroll
    for (int i = 0; i < NODES_PER_WARP; i++) {
        float p = x[i].x * w4.x + x[i].y * w4.y + x[i].z * w4.z + x[i].w * w4.w;
        p += __shfl_xor_sync(0xffffffffu, p, 1);
        p += __shfl_xor_sync(0xffffffffu, p, 2);
        if (q == 0) {
            g_tscore[(n0 + i) * NUM_H + h] = p;
            g_segsum[(n0 + i) * NUM_H + h] = 0.0f;
        }
    }
}

// ---------------------------------------------------------------------------
// K2: fused copy + dot + LeakyReLU + exp + alpha numerator + segsum atomic.
// One warp per 4 edges (R6-proven config, scalar epilogue).
#define EDGES_PER_WARP 4
__global__ void k_edge(const float* __restrict__ message,
                       const int* __restrict__ target,
                       const float* __restrict__ weight,
                       float* __restrict__ out_msg,
                       float* __restrict__ out_alpha) {
    int gtid = blockIdx.x * blockDim.x + threadIdx.x;
    int warp = gtid >> 5;
    int lane = gtid & 31;
    int e0 = warp * EDGES_PER_WARP;
    if (e0 >= NUM_E) return;

    const float4* msg4 = reinterpret_cast<const float4*>(message);
    float4*       out4 = reinterpret_cast<float4*>(out_msg);

    float4 m[EDGES_PER_WARP];
#pragma unroll
    for (int i = 0; i < EDGES_PER_WARP; i++)
        m[i] = __ldcs(&msg4[(size_t)(e0 + i) * 32 + lane]);   // streaming read
#pragma unroll
    for (int i = 0; i < EDGES_PER_WARP; i++)
        __stcs(&out4[(size_t)(e0 + i) * 32 + lane], m[i]);    // streaming write

    int h = lane >> 2, q = lane & 3;
    float4 w4 = reinterpret_cast<const float4*>(weight)[h * 8 + q];  // msg half

#pragma unroll
    for (int i = 0; i < EDGES_PER_WARP; i++) {
        float p = m[i].x * w4.x + m[i].y * w4.y + m[i].z * w4.z + m[i].w * w4.w;
        p += __shfl_xor_sync(0xffffffffu, p, 1);
        p += __shfl_xor_sync(0xffffffffu, p, 2);
        if (q == 0) {
            int e = e0 + i;
            int t = target[e];
            float s = p + g_tscore[t * NUM_H + h];
            s = (s >= 0.0f) ? s : 0.01f * s;          // LeakyReLU
            float ex = __expf(s);                     // no max-shift (safe)
            out_alpha[e * NUM_H + h] = ex;            // keep L2-resident
            atomicAdd(&g_segsum[t * NUM_H + h], ex);  // no-return RED
        }
    }
}

// ---------------------------------------------------------------------------
// K2.5: reciprocal of segment sums (turns k_norm divisions into multiplies)
__global__ void k_recip() {
    int i = blockIdx.x * blockDim.x + threadIdx.x;
    if (i < NUM_N * NUM_H)
        g_segsum[i] = 1.0f / (g_segsum[i] + 1e-16f);
}

// ---------------------------------------------------------------------------
// K3: normalize alpha. One edge per thread (640k threads: max TLP to hide
// the random segsum gathers), recip multiply, streaming final store.
__global__ void k_norm(const int* __restrict__ target,
                       float* __restrict__ out_alpha) {
    int e = blockIdx.x * blockDim.x + threadIdx.x;
    if (e >= NUM_E) return;
    int t = target[e];

    float4* a4 = reinterpret_cast<float4*>(out_alpha);
    float4 a0 = a4[e * 2 + 0];
    float4 a1 = a4[e * 2 + 1];

    const float4* rs4 = reinterpret_cast<const float4*>(g_segsum);
    float4 r0 = rs4[t * 2 + 0];
    float4 r1 = rs4[t * 2 + 1];

    a0.x *= r0.x; a0.y *= r0.y; a0.z *= r0.z; a0.w *= r0.w;
    a1.x *= r1.x; a1.y *= r1.y; a1.z *= r1.z; a1.w *= r1.w;

    __stcs(&a4[e * 2 + 0], a0);   // final output: never re-read
    __stcs(&a4[e * 2 + 1], a1);
}

// ---------------------------------------------------------------------------
extern "C" void kernel_launch(void* const* d_in, const int* in_sizes, int n_in,
                              void* d_out, int out_size) {
    const int*   edge_index = (const int*)d_in[0];    // (2, E) int32
    const float* message    = (const float*)d_in[1];  // (E, 128)
    const float* x_e        = (const float*)d_in[2];  // (N, 128)
    const float* weight     = (const float*)d_in[3];  // (8, 32)

    const int* target = edge_index + NUM_E;  // row 1

    float* out_msg   = (float*)d_out;                  // E*128 floats
    float* out_alpha = out_msg + (size_t)NUM_E * 128;  // E*8 floats

    const int TPB = 256;

    {   // k_tscore: one warp per 4 nodes
        int warps = (NUM_N + NODES_PER_WARP - 1) / NODES_PER_WARP;  // 5000
        k_tscore<<<(warps * 32 + TPB - 1) / TPB, TPB>>>(x_e, weight);
    }
    {   // k_edge: one warp per 4 edges
        int warps = NUM_E / EDGES_PER_WARP;              // 160000
        k_edge<<<(warps * 32 + TPB - 1) / TPB, TPB>>>(message, target, weight,
                                                      out_msg, out_alpha);
    }
    k_recip<<<(NUM_N * NUM_H + TPB - 1) / TPB, TPB>>>();
    k_norm<<<(NUM_E + TPB - 1) / TPB, TPB>>>(target, out_alpha);
}

// round 9
// speedup vs baseline: 1.0487x; 1.0312x over previous
#include <cuda_runtime.h>
#include <math.h>

#define NUM_E 640000
#define NUM_N 20000
#define NUM_H 8

// Scratch (allocation-free rule: __device__ globals)
__device__ __align__(16) float g_tscore[NUM_N * NUM_H];  // x_e[t] . w[h,16:]
__device__ __align__(16) float g_segsum[NUM_N * NUM_H];  // sum(exp) then recip

// ---------------------------------------------------------------------------
// K1: per-node target scores + zero segsum. One warp per 4 nodes.
#define NODES_PER_WARP 4
__global__ void k_tscore(const float* __restrict__ x_e,
                         const float* __restrict__ weight) {
    int gtid = blockIdx.x * blockDim.x + threadIdx.x;
    int warp = gtid >> 5;
    int lane = gtid & 31;
    int n0 = warp * NODES_PER_WARP;
    if (n0 >= NUM_N) return;

    const float4* x4p = reinterpret_cast<const float4*>(x_e);
    float4 x[NODES_PER_WARP];
#pragma unroll
    for (int i = 0; i < NODES_PER_WARP; i++)
        x[i] = x4p[(size_t)(n0 + i) * 32 + lane];

    int h = lane >> 2, q = lane & 3;
    float4 w4 = reinterpret_cast<const float4*>(weight)[h * 8 + 4 + q];

#pragma unroll
    for (int i = 0; i < NODES_PER_WARP; i++) {
        float p = x[i].x * w4.x + x[i].y * w4.y + x[i].z * w4.z + x[i].w * w4.w;
        p += __shfl_xor_sync(0xffffffffu, p, 1);
        p += __shfl_xor_sync(0xffffffffu, p, 2);
        if (q == 0) {
            g_tscore[(n0 + i) * NUM_H + h] = p;
            g_segsum[(n0 + i) * NUM_H + h] = 0.0f;
        }
    }
}

// ---------------------------------------------------------------------------
// K2: fused copy + dot + LeakyReLU + exp + alpha numerator + segsum atomic.
// One warp per 4 edges (R6/R8-proven config, scalar epilogue).
#define EDGES_PER_WARP 4
__global__ void k_edge(const float* __restrict__ message,
                       const int* __restrict__ target,
                       const float* __restrict__ weight,
                       float* __restrict__ out_msg,
                       float* __restrict__ out_alpha) {
    int gtid = blockIdx.x * blockDim.x + threadIdx.x;
    int warp = gtid >> 5;
    int lane = gtid & 31;
    int e0 = warp * EDGES_PER_WARP;
    if (e0 >= NUM_E) return;

    const float4* msg4 = reinterpret_cast<const float4*>(message);
    float4*       out4 = reinterpret_cast<float4*>(out_msg);

    float4 m[EDGES_PER_WARP];
#pragma unroll
    for (int i = 0; i < EDGES_PER_WARP; i++)
        m[i] = __ldcs(&msg4[(size_t)(e0 + i) * 32 + lane]);   // streaming read
#pragma unroll
    for (int i = 0; i < EDGES_PER_WARP; i++)
        __stcs(&out4[(size_t)(e0 + i) * 32 + lane], m[i]);    // streaming write

    int h = lane >> 2, q = lane & 3;
    float4 w4 = reinterpret_cast<const float4*>(weight)[h * 8 + q];  // msg half

#pragma unroll
    for (int i = 0; i < EDGES_PER_WARP; i++) {
        float p = m[i].x * w4.x + m[i].y * w4.y + m[i].z * w4.z + m[i].w * w4.w;
        p += __shfl_xor_sync(0xffffffffu, p, 1);
        p += __shfl_xor_sync(0xffffffffu, p, 2);
        if (q == 0) {
            int e = e0 + i;
            int t = target[e];
            float s = p + g_tscore[t * NUM_H + h];
            s = (s >= 0.0f) ? s : 0.01f * s;          // LeakyReLU
            float ex = __expf(s);                     // no max-shift (safe)
            out_alpha[e * NUM_H + h] = ex;            // keep L2-resident
            atomicAdd(&g_segsum[t * NUM_H + h], ex);  // no-return RED
        }
    }
}

// ---------------------------------------------------------------------------
// K2.5: reciprocal of segment sums (turns k_norm divisions into multiplies)
__global__ void k_recip() {
    int i = blockIdx.x * blockDim.x + threadIdx.x;
    if (i < NUM_N * NUM_H)
        g_segsum[i] = 1.0f / (g_segsum[i] + 1e-16f);
}

// ---------------------------------------------------------------------------
// K3: normalize alpha. TWO threads per edge (1.28M threads) — each handles
// one float4 half. Halves the per-thread dependency chain, doubles TLP.
__global__ void k_norm(const int* __restrict__ target,
                       float* __restrict__ out_alpha) {
    int idx = blockIdx.x * blockDim.x + threadIdx.x;   // [0, 2*NUM_E)
    if (idx >= 2 * NUM_E) return;
    int e    = idx >> 1;
    int t = target[e];                 // pair-coalesced broadcast load

    float4* a4 = reinterpret_cast<float4*>(out_alpha);
    float4 a = a4[idx];                // alpha half (L2-hot)

    const float4* rs4 = reinterpret_cast<const float4*>(g_segsum);
    float4 r = rs4[t * 2 + (idx & 1)]; // recip half (L2-hot table)

    a.x *= r.x; a.y *= r.y; a.z *= r.z; a.w *= r.w;

    __stcs(&a4[idx], a);               // final output: never re-read
}

// ---------------------------------------------------------------------------
extern "C" void kernel_launch(void* const* d_in, const int* in_sizes, int n_in,
                              void* d_out, int out_size) {
    const int*   edge_index = (const int*)d_in[0];    // (2, E) int32
    const float* message    = (const float*)d_in[1];  // (E, 128)
    const float* x_e        = (const float*)d_in[2];  // (N, 128)
    const float* weight     = (const float*)d_in[3];  // (8, 32)

    const int* target = edge_index + NUM_E;  // row 1

    float* out_msg   = (float*)d_out;                  // E*128 floats
    float* out_alpha = out_msg + (size_t)NUM_E * 128;  // E*8 floats

    const int TPB = 256;

    {   // k_tscore: one warp per 4 nodes
        int warps = (NUM_N + NODES_PER_WARP - 1) / NODES_PER_WARP;  // 5000
        k_tscore<<<(warps * 32 + TPB - 1) / TPB, TPB>>>(x_e, weight);
    }
    {   // k_edge: one warp per 4 edges
        int warps = NUM_E / EDGES_PER_WARP;              // 160000
        k_edge<<<(warps * 32 + TPB - 1) / TPB, TPB>>>(message, target, weight,
                                                      out_msg, out_alpha);
    }
    k_recip<<<(NUM_N * NUM_H + TPB - 1) / TPB, TPB>>>();
    k_norm<<<(2 * NUM_E + TPB - 1) / TPB, TPB>>>(target, out_alpha);
}